// round 7
// baseline (speedup 1.0000x reference)
#include <cuda_runtime.h>
#include <cstdint>

#define H_DIM   4096
#define R_DIM   16
#define N_TOK   32768
#define NTHREADS 256
#define KSCALE ((float)(2.0 / 0.95))
#define PDROP  0.05f

#define TB2     8              // tokens per block (kernel2, R4-proven)

__device__ float g_mid[N_TOK * R_DIM];        // 2 MB scratch
__device__ float g_bt[8 * R_DIM * H_DIM];     // 2 MB: Bt[e][r][h]

// ---------------------------------------------------------------------------
// Kernel 0: transpose lora_b[e][h][r] -> g_bt[e][r][h]  (~6us, one-shot)
// ---------------------------------------------------------------------------
__global__ void transpose_b_kernel(const float* __restrict__ lora_b)
{
    const int idx = blockIdx.x * blockDim.x + threadIdx.x;   // 524288
    const int r = idx & 15;
    const int h = (idx >> 4) & 4095;
    const int e = idx >> 16;
    g_bt[((size_t)e * R_DIM + r) * H_DIM + h] = lora_b[idx];
}

// ---------------------------------------------------------------------------
// Kernel 1: mid[g][r] = sum_h dropped(g,h) * A[e][r][h]
// 4 groups x 2 warps; each group = R4's proven inner loop over 4 tokens,
// 64 lanes covering 256 floats/iter, 16 iterations. Block = 16 tokens.
// All groups walk the same h-sequence -> A dedups in L1; A L2 traffic
// = 256KB x 2048 blocks = 0.5GB (was 2GB in R4).
// ---------------------------------------------------------------------------
__global__ __launch_bounds__(NTHREADS)
void lora_mid_kernel(const float* __restrict__ data,
                     const float* __restrict__ mask,
                     const float* __restrict__ lora_a)
{
    const int tid  = threadIdx.x;
    const int wid  = tid >> 5;
    const int lane = tid & 31;
    const int grp  = wid >> 1;            // 0..3
    const int li   = (tid & 63);          // lane within 2-warp group (0..63)
    const int gbase = blockIdx.x * 16;    // first token of block
    const int g0   = gbase + grp * 4;     // first token of group
    const int e    = blockIdx.x >> 8;     // 2048 blocks, 256 per expert
    const float* aBase = lora_a + (size_t)e * (R_DIM * H_DIM);

    float acc[4][R_DIM];
#pragma unroll
    for (int t = 0; t < 4; t++)
#pragma unroll
        for (int r = 0; r < R_DIM; r++) acc[t][r] = 0.f;

#pragma unroll 2
    for (int it = 0; it < H_DIM / (4 * 64); it++) {   // 16 iterations
        const int h4 = (it * 64 + li) * 4;

        float4 dr[4];
#pragma unroll
        for (int t = 0; t < 4; t++) {
            const size_t off = (size_t)(g0 + t) * H_DIM + h4;
            float4 x = __ldcs((const float4*)(data + off));
            float4 m = __ldcs((const float4*)(mask + off));
            dr[t].x = (m.x >= PDROP) ? x.x * KSCALE : 0.f;
            dr[t].y = (m.y >= PDROP) ? x.y * KSCALE : 0.f;
            dr[t].z = (m.z >= PDROP) ? x.z * KSCALE : 0.f;
            dr[t].w = (m.w >= PDROP) ? x.w * KSCALE : 0.f;
        }

#pragma unroll
        for (int r = 0; r < R_DIM; r++) {
            const float4 a4 = *(const float4*)(aBase + r * H_DIM + h4);
#pragma unroll
            for (int t = 0; t < 4; t++) {
                acc[t][r] += dr[t].x * a4.x + dr[t].y * a4.y
                           + dr[t].z * a4.z + dr[t].w * a4.w;
            }
        }
    }

    // Butterfly reduce within each warp
#pragma unroll
    for (int t = 0; t < 4; t++)
#pragma unroll
        for (int r = 0; r < R_DIM; r++) {
#pragma unroll
            for (int off = 16; off > 0; off >>= 1)
                acc[t][r] += __shfl_xor_sync(0xffffffffu, acc[t][r], off);
        }

    // Combine the 2 warps of each group via smem
    __shared__ float red[8][64];
    if (lane == 0) {
#pragma unroll
        for (int t = 0; t < 4; t++)
#pragma unroll
            for (int r = 0; r < R_DIM; r++)
                red[wid][t * R_DIM + r] = acc[t][r];
    }
    __syncthreads();

    // 256 threads = 4 groups x 64 values: final add + store
    {
        const int og  = tid >> 6;          // group 0..3
        const int idx = tid & 63;          // t*16+r
        const float v = red[2 * og][idx] + red[2 * og + 1][idx];
        g_mid[(size_t)(gbase + og * 4) * R_DIM + idx] = v;
    }
}

// ---------------------------------------------------------------------------
// Kernel 2: out[g][h] = result[g][h] + sum_r mid[g][r] * Bt[e][r][h]
// R4-proven version, unchanged. TB2=8, coalesced Bt float4 reused x8,
// mid in smem, float4 streaming result/out. grid = (N_TOK/8, H/1024)
// ---------------------------------------------------------------------------
__global__ __launch_bounds__(NTHREADS)
void lora_out_kernel(const float* __restrict__ result,
                     float* __restrict__ out)
{
    const int tid = threadIdx.x;
    const int g0  = blockIdx.x * TB2;
    const int e   = g0 >> 12;
    const int h4  = (blockIdx.y * NTHREADS + tid) * 4;
    const float* btBase = g_bt + (size_t)e * (R_DIM * H_DIM);

    __shared__ float smid[TB2 * R_DIM];
    if (tid < TB2 * R_DIM)
        smid[tid] = g_mid[(size_t)g0 * R_DIM + tid];
    __syncthreads();

    float4 acc[TB2];
#pragma unroll
    for (int t = 0; t < TB2; t++)
        acc[t] = __ldcs((const float4*)(result + (size_t)(g0 + t) * H_DIM + h4));

#pragma unroll
    for (int r = 0; r < R_DIM; r++) {
        const float4 b4 = *(const float4*)(btBase + (size_t)r * H_DIM + h4);
#pragma unroll
        for (int t = 0; t < TB2; t++) {
            const float m = smid[t * R_DIM + r];
            acc[t].x += m * b4.x;
            acc[t].y += m * b4.y;
            acc[t].z += m * b4.z;
            acc[t].w += m * b4.w;
        }
    }

#pragma unroll
    for (int t = 0; t < TB2; t++)
        __stcs((float4*)(out + (size_t)(g0 + t) * H_DIM + h4), acc[t]);
}

// ---------------------------------------------------------------------------
extern "C" void kernel_launch(void* const* d_in, const int* in_sizes, int n_in,
                              void* d_out, int out_size)
{
    const float* result   = (const float*)d_in[0];
    const float* data     = (const float*)d_in[1];
    const float* dropmask = (const float*)d_in[2];
    const float* lora_a   = (const float*)d_in[3];
    const float* lora_b   = (const float*)d_in[4];
    float* out = (float*)d_out;

    transpose_b_kernel<<<(8 * R_DIM * H_DIM) / NTHREADS, NTHREADS>>>(lora_b);
    lora_mid_kernel<<<N_TOK / 16, NTHREADS>>>(data, dropmask, lora_a);

    dim3 grid2(N_TOK / TB2, H_DIM / (4 * NTHREADS));
    lora_out_kernel<<<grid2, NTHREADS>>>(result, out);
}

// round 8
// speedup vs baseline: 1.1992x; 1.1992x over previous
#include <cuda_runtime.h>
#include <cstdint>

#define H_DIM   4096
#define R_DIM   16
#define N_TOK   32768          // B*S
#define TB      4              // tokens per block (kernel1, R4-proven)
#define TB2     8              // tokens per block (kernel2, R4-proven)
#define NTHREADS 256
#define KSCALE ((float)(2.0 / 0.95))
#define PDROP  0.05f

__device__ float g_mid[N_TOK * R_DIM];        // 2 MB scratch
__device__ float g_bt[8 * R_DIM * H_DIM];     // 2 MB: Bt[e][r][h] (pre-scaled)

// ---------------------------------------------------------------------------
// Kernel 0: transpose + prescale: g_bt[e][r][h] = KSCALE * lora_b[e][h][r]
// Folding KSCALE here deletes one FMUL per element from kernel1's hot loop.
// ---------------------------------------------------------------------------
__global__ void transpose_b_kernel(const float* __restrict__ lora_b)
{
    const int idx = blockIdx.x * blockDim.x + threadIdx.x;   // 524288
    const int r = idx & 15;
    const int h = (idx >> 4) & 4095;
    const int e = idx >> 16;
    g_bt[((size_t)e * R_DIM + r) * H_DIM + h] = KSCALE * lora_b[idx];
}

// ---------------------------------------------------------------------------
// Kernel 1: mid[g][r] = sum_h (keep? data : 0) * A[e][r][h]   (KSCALE folded
// into Bt). R4-proven shape: TB=4 tokens/block, 256 threads stride full H,
// 4 fully-unrolled iterations, acc[4][16] in regs, launch_bounds(256,2).
// ---------------------------------------------------------------------------
__global__ __launch_bounds__(NTHREADS, 2)
void lora_mid_kernel(const float* __restrict__ data,
                     const float* __restrict__ mask,
                     const float* __restrict__ lora_a)
{
    const int tid = threadIdx.x;
    const int g0  = blockIdx.x * TB;
    const int e   = g0 >> 12;
    const float* aBase = lora_a + (size_t)e * (R_DIM * H_DIM);

    float acc[TB][R_DIM];
#pragma unroll
    for (int t = 0; t < TB; t++)
#pragma unroll
        for (int r = 0; r < R_DIM; r++) acc[t][r] = 0.f;

#pragma unroll
    for (int it = 0; it < H_DIM / (4 * NTHREADS); it++) {
        const int h4 = (it * NTHREADS + tid) * 4;

        float4 dr[TB];
#pragma unroll
        for (int t = 0; t < TB; t++) {
            const size_t off = (size_t)(g0 + t) * H_DIM + h4;
            float4 x = __ldcs((const float4*)(data + off));
            float4 m = __ldcs((const float4*)(mask + off));
            dr[t].x = (m.x >= PDROP) ? x.x : 0.f;
            dr[t].y = (m.y >= PDROP) ? x.y : 0.f;
            dr[t].z = (m.z >= PDROP) ? x.z : 0.f;
            dr[t].w = (m.w >= PDROP) ? x.w : 0.f;
        }

#pragma unroll
        for (int r = 0; r < R_DIM; r++) {
            const float4 a4 = *(const float4*)(aBase + r * H_DIM + h4);
#pragma unroll
            for (int t = 0; t < TB; t++) {
                acc[t][r] += dr[t].x * a4.x + dr[t].y * a4.y
                           + dr[t].z * a4.z + dr[t].w * a4.w;
            }
        }
    }

    // Intra-warp butterfly reduction
#pragma unroll
    for (int t = 0; t < TB; t++)
#pragma unroll
        for (int r = 0; r < R_DIM; r++) {
#pragma unroll
            for (int off = 16; off > 0; off >>= 1)
                acc[t][r] += __shfl_xor_sync(0xffffffffu, acc[t][r], off);
        }

    // Cross-warp via smem
    __shared__ float red[8][TB * R_DIM];
    const int wid  = tid >> 5;
    const int lane = tid & 31;
    if (lane == 0) {
#pragma unroll
        for (int t = 0; t < TB; t++)
#pragma unroll
            for (int r = 0; r < R_DIM; r++)
                red[wid][t * R_DIM + r] = acc[t][r];
    }
    __syncthreads();

    if (tid < TB * R_DIM) {
        float s = 0.f;
#pragma unroll
        for (int w = 0; w < 8; w++) s += red[w][tid];
        g_mid[(size_t)g0 * R_DIM + tid] = s;   // contiguous [t][r]
    }
}

// ---------------------------------------------------------------------------
// Kernel 2: out[g][h] = result[g][h] + sum_r mid[g][r] * Bt[e][r][h]
// R4-proven version, byte-identical. TB2=8, coalesced Bt float4 reused x8,
// mid in smem, float4 streaming result/out. grid = (N_TOK/8, H/1024)
// ---------------------------------------------------------------------------
__global__ __launch_bounds__(NTHREADS)
void lora_out_kernel(const float* __restrict__ result,
                     float* __restrict__ out)
{
    const int tid = threadIdx.x;
    const int g0  = blockIdx.x * TB2;
    const int e   = g0 >> 12;
    const int h4  = (blockIdx.y * NTHREADS + tid) * 4;
    const float* btBase = g_bt + (size_t)e * (R_DIM * H_DIM);

    __shared__ float smid[TB2 * R_DIM];
    if (tid < TB2 * R_DIM)
        smid[tid] = g_mid[(size_t)g0 * R_DIM + tid];
    __syncthreads();

    float4 acc[TB2];
#pragma unroll
    for (int t = 0; t < TB2; t++)
        acc[t] = __ldcs((const float4*)(result + (size_t)(g0 + t) * H_DIM + h4));

#pragma unroll
    for (int r = 0; r < R_DIM; r++) {
        const float4 b4 = *(const float4*)(btBase + (size_t)r * H_DIM + h4);
#pragma unroll
        for (int t = 0; t < TB2; t++) {
            const float m = smid[t * R_DIM + r];
            acc[t].x += m * b4.x;
            acc[t].y += m * b4.y;
            acc[t].z += m * b4.z;
            acc[t].w += m * b4.w;
        }
    }

#pragma unroll
    for (int t = 0; t < TB2; t++)
        __stcs((float4*)(out + (size_t)(g0 + t) * H_DIM + h4), acc[t]);
}

// ---------------------------------------------------------------------------
extern "C" void kernel_launch(void* const* d_in, const int* in_sizes, int n_in,
                              void* d_out, int out_size)
{
    const float* result   = (const float*)d_in[0];
    const float* data     = (const float*)d_in[1];
    const float* dropmask = (const float*)d_in[2];
    const float* lora_a   = (const float*)d_in[3];
    const float* lora_b   = (const float*)d_in[4];
    float* out = (float*)d_out;

    transpose_b_kernel<<<(8 * R_DIM * H_DIM) / NTHREADS, NTHREADS>>>(lora_b);
    lora_mid_kernel<<<N_TOK / TB, NTHREADS>>>(data, dropmask, lora_a);

    dim3 grid2(N_TOK / TB2, H_DIM / (4 * NTHREADS));
    lora_out_kernel<<<grid2, NTHREADS>>>(result, out);
}

// round 9
// speedup vs baseline: 1.2877x; 1.0738x over previous
#include <cuda_runtime.h>
#include <cstdint>

#define H_DIM   4096
#define R_DIM   16
#define N_TOK   32768          // B*S
#define TB      4              // tokens per block (kernel1, R4-proven)
#define TB2     16             // tokens per block (kernel2) -- the ONE change
#define NTHREADS 256
#define KSCALE ((float)(2.0 / 0.95))
#define PDROP  0.05f

__device__ float g_mid[N_TOK * R_DIM];        // 2 MB scratch
__device__ float g_bt[8 * R_DIM * H_DIM];     // 2 MB: Bt[e][r][h]

// ---------------------------------------------------------------------------
// Kernel 0: transpose lora_b[e][h][r] -> g_bt[e][r][h]  (R4-exact, ~6us)
// ---------------------------------------------------------------------------
__global__ void transpose_b_kernel(const float* __restrict__ lora_b)
{
    const int idx = blockIdx.x * blockDim.x + threadIdx.x;   // 524288
    const int r = idx & 15;
    const int h = (idx >> 4) & 4095;
    const int e = idx >> 16;
    g_bt[((size_t)e * R_DIM + r) * H_DIM + h] = lora_b[idx];
}

// ---------------------------------------------------------------------------
// Kernel 1: mid[g][r] = sum_h dropped(g,h) * A[e][r][h]   (R4-exact)
// ---------------------------------------------------------------------------
__global__ __launch_bounds__(NTHREADS, 2)
void lora_mid_kernel(const float* __restrict__ data,
                     const float* __restrict__ mask,
                     const float* __restrict__ lora_a)
{
    const int tid = threadIdx.x;
    const int g0  = blockIdx.x * TB;
    const int e   = g0 >> 12;
    const float* aBase = lora_a + (size_t)e * (R_DIM * H_DIM);

    float acc[TB][R_DIM];
#pragma unroll
    for (int t = 0; t < TB; t++)
#pragma unroll
        for (int r = 0; r < R_DIM; r++) acc[t][r] = 0.f;

#pragma unroll
    for (int it = 0; it < H_DIM / (4 * NTHREADS); it++) {
        const int h4 = (it * NTHREADS + tid) * 4;

        float4 dr[TB];
#pragma unroll
        for (int t = 0; t < TB; t++) {
            const size_t off = (size_t)(g0 + t) * H_DIM + h4;
            float4 x = __ldcs((const float4*)(data + off));
            float4 m = __ldcs((const float4*)(mask + off));
            dr[t].x = (m.x >= PDROP) ? x.x * KSCALE : 0.f;
            dr[t].y = (m.y >= PDROP) ? x.y * KSCALE : 0.f;
            dr[t].z = (m.z >= PDROP) ? x.z * KSCALE : 0.f;
            dr[t].w = (m.w >= PDROP) ? x.w * KSCALE : 0.f;
        }

#pragma unroll
        for (int r = 0; r < R_DIM; r++) {
            const float4 a4 = *(const float4*)(aBase + r * H_DIM + h4);
#pragma unroll
            for (int t = 0; t < TB; t++) {
                acc[t][r] += dr[t].x * a4.x + dr[t].y * a4.y
                           + dr[t].z * a4.z + dr[t].w * a4.w;
            }
        }
    }

    // Intra-warp butterfly reduction
#pragma unroll
    for (int t = 0; t < TB; t++)
#pragma unroll
        for (int r = 0; r < R_DIM; r++) {
#pragma unroll
            for (int off = 16; off > 0; off >>= 1)
                acc[t][r] += __shfl_xor_sync(0xffffffffu, acc[t][r], off);
        }

    // Cross-warp via smem
    __shared__ float red[8][TB * R_DIM];
    const int wid  = tid >> 5;
    const int lane = tid & 31;
    if (lane == 0) {
#pragma unroll
        for (int t = 0; t < TB; t++)
#pragma unroll
            for (int r = 0; r < R_DIM; r++)
                red[wid][t * R_DIM + r] = acc[t][r];
    }
    __syncthreads();

    if (tid < TB * R_DIM) {
        float s = 0.f;
#pragma unroll
        for (int w = 0; w < 8; w++) s += red[w][tid];
        g_mid[(size_t)g0 * R_DIM + tid] = s;
    }
}

// ---------------------------------------------------------------------------
// Kernel 2: out[g][h] = result[g][h] + sum_r mid[g][r] * Bt[e][r][h]
// TB2=16 (halves Bt L2 traffic vs R4), scalar float4 accs (64 regs, no
// f32x2/no spills), result loads in 2 batches of 8 to bound MLP_p1.
// grid = (N_TOK/16, H/1024)
// ---------------------------------------------------------------------------
__global__ __launch_bounds__(NTHREADS)
void lora_out_kernel(const float* __restrict__ result,
                     float* __restrict__ out)
{
    const int tid = threadIdx.x;
    const int g0  = blockIdx.x * TB2;
    const int e   = g0 >> 12;
    const int h4  = (blockIdx.y * NTHREADS + tid) * 4;
    const float* btBase = g_bt + (size_t)e * (R_DIM * H_DIM);

    __shared__ float smid[TB2 * R_DIM];   // 256 floats
    smid[tid] = g_mid[(size_t)g0 * R_DIM + tid];
    __syncthreads();

    float4 acc[TB2];
    // batch 1: tokens 0..7
#pragma unroll
    for (int t = 0; t < 8; t++)
        acc[t] = __ldcs((const float4*)(result + (size_t)(g0 + t) * H_DIM + h4));

#pragma unroll
    for (int r = 0; r < R_DIM; r++) {
        const float4 b4 = *(const float4*)(btBase + (size_t)r * H_DIM + h4);
#pragma unroll
        for (int t = 0; t < 8; t++) {
            const float m = smid[t * R_DIM + r];
            acc[t].x += m * b4.x;
            acc[t].y += m * b4.y;
            acc[t].z += m * b4.z;
            acc[t].w += m * b4.w;
        }
    }
#pragma unroll
    for (int t = 0; t < 8; t++)
        __stcs((float4*)(out + (size_t)(g0 + t) * H_DIM + h4), acc[t]);

    // batch 2: tokens 8..15 (Bt slice re-read hits L1)
#pragma unroll
    for (int t = 8; t < TB2; t++)
        acc[t] = __ldcs((const float4*)(result + (size_t)(g0 + t) * H_DIM + h4));

#pragma unroll
    for (int r = 0; r < R_DIM; r++) {
        const float4 b4 = *(const float4*)(btBase + (size_t)r * H_DIM + h4);
#pragma unroll
        for (int t = 8; t < TB2; t++) {
            const float m = smid[t * R_DIM + r];
            acc[t].x += m * b4.x;
            acc[t].y += m * b4.y;
            acc[t].z += m * b4.z;
            acc[t].w += m * b4.w;
        }
    }
#pragma unroll
    for (int t = 8; t < TB2; t++)
        __stcs((float4*)(out + (size_t)(g0 + t) * H_DIM + h4), acc[t]);
}

// ---------------------------------------------------------------------------
extern "C" void kernel_launch(void* const* d_in, const int* in_sizes, int n_in,
                              void* d_out, int out_size)
{
    const float* result   = (const float*)d_in[0];
    const float* data     = (const float*)d_in[1];
    const float* dropmask = (const float*)d_in[2];
    const float* lora_a   = (const float*)d_in[3];
    const float* lora_b   = (const float*)d_in[4];
    float* out = (float*)d_out;

    transpose_b_kernel<<<(8 * R_DIM * H_DIM) / NTHREADS, NTHREADS>>>(lora_b);
    lora_mid_kernel<<<N_TOK / TB, NTHREADS>>>(data, dropmask, lora_a);

    dim3 grid2(N_TOK / TB2, H_DIM / (4 * NTHREADS));
    lora_out_kernel<<<grid2, NTHREADS>>>(result, out);
}

// round 10
// speedup vs baseline: 1.3888x; 1.0786x over previous
#include <cuda_runtime.h>
#include <cstdint>

#define H_DIM   4096
#define R_DIM   16
#define N_TOK   32768          // B*S
#define TB2     16             // tokens per block (kernel2, R9-proven)
#define NTHREADS 256
#define KSCALE ((float)(2.0 / 0.95))
#define PDROP  0.05f

// kernel1 (new): 16 tokens/block, H in 32 chunks of 128 floats
#define K1_TB   16
#define K1_C    128
#define K1_NCH  (H_DIM / K1_C)   // 32

__device__ float g_mid[N_TOK * R_DIM];        // 2 MB scratch
__device__ float g_bt[8 * R_DIM * H_DIM];     // 2 MB: Bt[e][r][h]

// ---------------------------------------------------------------------------
// Kernel 0: transpose lora_b[e][h][r] -> g_bt[e][r][h]  (R9-exact, ~6us)
// ---------------------------------------------------------------------------
__global__ void transpose_b_kernel(const float* __restrict__ lora_b)
{
    const int idx = blockIdx.x * blockDim.x + threadIdx.x;   // 524288
    const int r = idx & 15;
    const int h = (idx >> 4) & 4095;
    const int e = idx >> 16;
    g_bt[((size_t)e * R_DIM + r) * H_DIM + h] = lora_b[idx];
}

// ---------------------------------------------------------------------------
// Kernel 1 (NEW): mid[g][r] = sum_h dropped(g,h) * A[e][r][h]
// 16 tokens/block. Dropped data staged in smem (double-buffered 8KB chunks).
// Warp w owns r = {2w, 2w+1} for ALL 16 tokens: A is read from gmem EXACTLY
// once per block (256KB) -> A L2 traffic 0.5GB (was 2GB). acc[16][2]=32 regs.
// LDS reads are row-broadcast float4, conflict-free.
// ---------------------------------------------------------------------------
__global__ __launch_bounds__(NTHREADS)
void lora_mid_kernel(const float* __restrict__ data,
                     const float* __restrict__ mask,
                     const float* __restrict__ lora_a)
{
    const int tid  = threadIdx.x;
    const int wid  = tid >> 5;           // 0..7  -> owns r = 2*wid, 2*wid+1
    const int lane = tid & 31;
    const int g0   = blockIdx.x * K1_TB;
    const int e    = blockIdx.x >> 8;    // 256 blocks per expert
    const float* a0Base = lora_a + ((size_t)e * R_DIM + 2 * wid    ) * H_DIM;
    const float* a1Base = lora_a + ((size_t)e * R_DIM + 2 * wid + 1) * H_DIM;

    // staging assignment: thread -> (token, float4-slot f and f+16)
    const int stok = tid >> 4;           // 0..15
    const int sf   = tid & 15;           // 0..15

    __shared__ float4 sbuf[2][K1_TB][K1_C / 4];   // 2 x 16 x 32 float4 = 16KB

    float acc[K1_TB][2];
#pragma unroll
    for (int t = 0; t < K1_TB; t++) { acc[t][0] = 0.f; acc[t][1] = 0.f; }

    // prefetch chunk 0
    float4 dx0, dx1, mx0, mx1;
    {
        const size_t base = (size_t)(g0 + stok) * H_DIM;
        dx0 = __ldcs((const float4*)(data + base + sf * 4));
        dx1 = __ldcs((const float4*)(data + base + (sf + 16) * 4));
        mx0 = __ldcs((const float4*)(mask + base + sf * 4));
        mx1 = __ldcs((const float4*)(mask + base + (sf + 16) * 4));
    }

#pragma unroll 1
    for (int ch = 0; ch < K1_NCH; ch++) {
        const int buf = ch & 1;

        // dropout + stage to smem
        float4 d0, d1;
        d0.x = (mx0.x >= PDROP) ? dx0.x * KSCALE : 0.f;
        d0.y = (mx0.y >= PDROP) ? dx0.y * KSCALE : 0.f;
        d0.z = (mx0.z >= PDROP) ? dx0.z * KSCALE : 0.f;
        d0.w = (mx0.w >= PDROP) ? dx0.w * KSCALE : 0.f;
        d1.x = (mx1.x >= PDROP) ? dx1.x * KSCALE : 0.f;
        d1.y = (mx1.y >= PDROP) ? dx1.y * KSCALE : 0.f;
        d1.z = (mx1.z >= PDROP) ? dx1.z * KSCALE : 0.f;
        d1.w = (mx1.w >= PDROP) ? dx1.w * KSCALE : 0.f;
        sbuf[buf][stok][sf]      = d0;
        sbuf[buf][stok][sf + 16] = d1;

        // prefetch next chunk (clamped; chunk 31 reloads itself harmlessly)
        {
            const int nch = (ch + 1 < K1_NCH) ? ch + 1 : ch;
            const size_t base = (size_t)(g0 + stok) * H_DIM + (size_t)nch * K1_C;
            dx0 = __ldcs((const float4*)(data + base + sf * 4));
            dx1 = __ldcs((const float4*)(data + base + (sf + 16) * 4));
            mx0 = __ldcs((const float4*)(mask + base + sf * 4));
            mx1 = __ldcs((const float4*)(mask + base + (sf + 16) * 4));
        }

        __syncthreads();

        // this warp's A slice for this chunk (read ONCE from gmem)
        const int hoff = ch * K1_C + lane * 4;
        const float4 a0 = *(const float4*)(a0Base + hoff);
        const float4 a1 = *(const float4*)(a1Base + hoff);

        // accumulate all 16 tokens
#pragma unroll
        for (int t = 0; t < K1_TB; t++) {
            const float4 v = sbuf[buf][t][lane];
            acc[t][0] += v.x * a0.x + v.y * a0.y + v.z * a0.z + v.w * a0.w;
            acc[t][1] += v.x * a1.x + v.y * a1.y + v.z * a1.z + v.w * a1.w;
        }

        __syncthreads();
    }

    // reduce over lanes (h) and store: warp w -> mid[*][2w], mid[*][2w+1]
#pragma unroll
    for (int t = 0; t < K1_TB; t++) {
#pragma unroll
        for (int j = 0; j < 2; j++) {
            float s = acc[t][j];
#pragma unroll
            for (int off = 16; off > 0; off >>= 1)
                s += __shfl_xor_sync(0xffffffffu, s, off);
            if (lane == 0)
                g_mid[(size_t)(g0 + t) * R_DIM + 2 * wid + j] = s;
        }
    }
}

// ---------------------------------------------------------------------------
// Kernel 2: out[g][h] = result[g][h] + sum_r mid[g][r] * Bt[e][r][h]
// R9-exact champion. TB2=16, two batches of 8 tokens.
// ---------------------------------------------------------------------------
__global__ __launch_bounds__(NTHREADS)
void lora_out_kernel(const float* __restrict__ result,
                     float* __restrict__ out)
{
    const int tid = threadIdx.x;
    const int g0  = blockIdx.x * TB2;
    const int e   = g0 >> 12;
    const int h4  = (blockIdx.y * NTHREADS + tid) * 4;
    const float* btBase = g_bt + (size_t)e * (R_DIM * H_DIM);

    __shared__ float smid[TB2 * R_DIM];
    smid[tid] = g_mid[(size_t)g0 * R_DIM + tid];
    __syncthreads();

    float4 acc[TB2];
#pragma unroll
    for (int t = 0; t < 8; t++)
        acc[t] = __ldcs((const float4*)(result + (size_t)(g0 + t) * H_DIM + h4));

#pragma unroll
    for (int r = 0; r < R_DIM; r++) {
        const float4 b4 = *(const float4*)(btBase + (size_t)r * H_DIM + h4);
#pragma unroll
        for (int t = 0; t < 8; t++) {
            const float m = smid[t * R_DIM + r];
            acc[t].x += m * b4.x;
            acc[t].y += m * b4.y;
            acc[t].z += m * b4.z;
            acc[t].w += m * b4.w;
        }
    }
#pragma unroll
    for (int t = 0; t < 8; t++)
        __stcs((float4*)(out + (size_t)(g0 + t) * H_DIM + h4), acc[t]);

#pragma unroll
    for (int t = 8; t < TB2; t++)
        acc[t] = __ldcs((const float4*)(result + (size_t)(g0 + t) * H_DIM + h4));

#pragma unroll
    for (int r = 0; r < R_DIM; r++) {
        const float4 b4 = *(const float4*)(btBase + (size_t)r * H_DIM + h4);
#pragma unroll
        for (int t = 8; t < TB2; t++) {
            const float m = smid[t * R_DIM + r];
            acc[t].x += m * b4.x;
            acc[t].y += m * b4.y;
            acc[t].z += m * b4.z;
            acc[t].w += m * b4.w;
        }
    }
#pragma unroll
    for (int t = 8; t < TB2; t++)
        __stcs((float4*)(out + (size_t)(g0 + t) * H_DIM + h4), acc[t]);
}

// ---------------------------------------------------------------------------
extern "C" void kernel_launch(void* const* d_in, const int* in_sizes, int n_in,
                              void* d_out, int out_size)
{
    const float* result   = (const float*)d_in[0];
    const float* data     = (const float*)d_in[1];
    const float* dropmask = (const float*)d_in[2];
    const float* lora_a   = (const float*)d_in[3];
    const float* lora_b   = (const float*)d_in[4];
    float* out = (float*)d_out;

    transpose_b_kernel<<<(8 * R_DIM * H_DIM) / NTHREADS, NTHREADS>>>(lora_b);
    lora_mid_kernel<<<N_TOK / K1_TB, NTHREADS>>>(data, dropmask, lora_a);

    dim3 grid2(N_TOK / TB2, H_DIM / (4 * NTHREADS));
    lora_out_kernel<<<grid2, NTHREADS>>>(result, out);
}

// round 11
// speedup vs baseline: 1.4231x; 1.0247x over previous
#include <cuda_runtime.h>
#include <cstdint>

#define H_DIM   4096
#define R_DIM   16
#define N_TOK   32768          // B*S
#define TB2     16             // tokens per block (kernel2, R9-proven)
#define NTHREADS 256
#define KSCALE ((float)(2.0 / 0.95))
#define PDROP  0.05f

// kernel1: 16 tokens/block, H in 32 chunks of 128 floats
#define K1_TB   16
#define K1_C    128
#define K1_NCH  (H_DIM / K1_C)   // 32

__device__ float g_mid[N_TOK * R_DIM];        // 2 MB scratch
__device__ float g_bt[8 * R_DIM * H_DIM];     // 2 MB: Bt[e][r][h]

// ---------------------------------------------------------------------------
// Kernel 0: transpose lora_b[e][h][r] -> g_bt[e][r][h]  (~6us)
// ---------------------------------------------------------------------------
__global__ void transpose_b_kernel(const float* __restrict__ lora_b)
{
    const int idx = blockIdx.x * blockDim.x + threadIdx.x;   // 524288
    const int r = idx & 15;
    const int h = (idx >> 4) & 4095;
    const int e = idx >> 16;
    g_bt[((size_t)e * R_DIM + r) * H_DIM + h] = lora_b[idx];
}

// ---------------------------------------------------------------------------
// Kernel 1: mid[g][r] = sum_h dropped(g,h) * A[e][r][h]
// 16 tokens/block, smem-staged dropped data (double-buffered).
// NEW partition: warp w -> token-group tg=w>>2 (8 tokens) x r-group rg=w&3
// (4 r's). acc[8][4]=32 regs. Per-warp l1tex wavefronts/chunk: 72 (was 96).
// A rows via gmem (L1-dedup across the 2 warps sharing rg); block A
// first-touch = 256KB -> A L2 traffic 0.5GB unchanged.
// ---------------------------------------------------------------------------
__global__ __launch_bounds__(NTHREADS)
void lora_mid_kernel(const float* __restrict__ data,
                     const float* __restrict__ mask,
                     const float* __restrict__ lora_a)
{
    const int tid  = threadIdx.x;
    const int wid  = tid >> 5;           // 0..7
    const int lane = tid & 31;
    const int tg   = wid >> 2;           // 0..1 : tokens [8*tg, 8*tg+8)
    const int rg   = wid & 3;            // 0..3 : r in [4*rg, 4*rg+4)
    const int g0   = blockIdx.x * K1_TB;
    const int e    = blockIdx.x >> 8;    // 256 blocks per expert
    const float* aBase = lora_a + ((size_t)e * R_DIM + 4 * rg) * H_DIM;

    // staging assignment: thread -> (token, float4-slot sf and sf+16)
    const int stok = tid >> 4;           // 0..15
    const int sf   = tid & 15;           // 0..15

    __shared__ float4 sbuf[2][K1_TB][K1_C / 4];   // 16KB

    float acc[8][4];
#pragma unroll
    for (int t = 0; t < 8; t++)
#pragma unroll
        for (int j = 0; j < 4; j++) acc[t][j] = 0.f;

    // prefetch chunk 0
    float4 dx0, dx1, mx0, mx1;
    {
        const size_t base = (size_t)(g0 + stok) * H_DIM;
        dx0 = __ldcs((const float4*)(data + base + sf * 4));
        dx1 = __ldcs((const float4*)(data + base + (sf + 16) * 4));
        mx0 = __ldcs((const float4*)(mask + base + sf * 4));
        mx1 = __ldcs((const float4*)(mask + base + (sf + 16) * 4));
    }

#pragma unroll 1
    for (int ch = 0; ch < K1_NCH; ch++) {
        const int buf = ch & 1;

        // dropout + stage to smem
        float4 d0, d1;
        d0.x = (mx0.x >= PDROP) ? dx0.x * KSCALE : 0.f;
        d0.y = (mx0.y >= PDROP) ? dx0.y * KSCALE : 0.f;
        d0.z = (mx0.z >= PDROP) ? dx0.z * KSCALE : 0.f;
        d0.w = (mx0.w >= PDROP) ? dx0.w * KSCALE : 0.f;
        d1.x = (mx1.x >= PDROP) ? dx1.x * KSCALE : 0.f;
        d1.y = (mx1.y >= PDROP) ? dx1.y * KSCALE : 0.f;
        d1.z = (mx1.z >= PDROP) ? dx1.z * KSCALE : 0.f;
        d1.w = (mx1.w >= PDROP) ? dx1.w * KSCALE : 0.f;
        sbuf[buf][stok][sf]      = d0;
        sbuf[buf][stok][sf + 16] = d1;

        // prefetch next chunk (chunk 31 reloads itself harmlessly)
        {
            const int nch = (ch + 1 < K1_NCH) ? ch + 1 : ch;
            const size_t base = (size_t)(g0 + stok) * H_DIM + (size_t)nch * K1_C;
            dx0 = __ldcs((const float4*)(data + base + sf * 4));
            dx1 = __ldcs((const float4*)(data + base + (sf + 16) * 4));
            mx0 = __ldcs((const float4*)(mask + base + sf * 4));
            mx1 = __ldcs((const float4*)(mask + base + (sf + 16) * 4));
        }

        __syncthreads();

        // this warp's 4 A rows for this chunk (gmem; L1-shared across warps)
        const int hoff = ch * K1_C + lane * 4;
        const float4 a0 = *(const float4*)(aBase + 0 * H_DIM + hoff);
        const float4 a1 = *(const float4*)(aBase + 1 * H_DIM + hoff);
        const float4 a2 = *(const float4*)(aBase + 2 * H_DIM + hoff);
        const float4 a3 = *(const float4*)(aBase + 3 * H_DIM + hoff);

        // accumulate this warp's 8 tokens x 4 r
#pragma unroll
        for (int t = 0; t < 8; t++) {
            const float4 v = sbuf[buf][8 * tg + t][lane];
            acc[t][0] += v.x * a0.x + v.y * a0.y + v.z * a0.z + v.w * a0.w;
            acc[t][1] += v.x * a1.x + v.y * a1.y + v.z * a1.z + v.w * a1.w;
            acc[t][2] += v.x * a2.x + v.y * a2.y + v.z * a2.z + v.w * a2.w;
            acc[t][3] += v.x * a3.x + v.y * a3.y + v.z * a3.z + v.w * a3.w;
        }

        __syncthreads();
    }

    // reduce over lanes (h) and store
#pragma unroll
    for (int t = 0; t < 8; t++) {
#pragma unroll
        for (int j = 0; j < 4; j++) {
            float s = acc[t][j];
#pragma unroll
            for (int off = 16; off > 0; off >>= 1)
                s += __shfl_xor_sync(0xffffffffu, s, off);
            if (lane == 0)
                g_mid[(size_t)(g0 + 8 * tg + t) * R_DIM + 4 * rg + j] = s;
        }
    }
}

// ---------------------------------------------------------------------------
// Kernel 2: out[g][h] = result[g][h] + sum_r mid[g][r] * Bt[e][r][h]
// R10-exact champion. TB2=16, two batches of 8 tokens.
// ---------------------------------------------------------------------------
__global__ __launch_bounds__(NTHREADS)
void lora_out_kernel(const float* __restrict__ result,
                     float* __restrict__ out)
{
    const int tid = threadIdx.x;
    const int g0  = blockIdx.x * TB2;
    const int e   = g0 >> 12;
    const int h4  = (blockIdx.y * NTHREADS + tid) * 4;
    const float* btBase = g_bt + (size_t)e * (R_DIM * H_DIM);

    __shared__ float smid[TB2 * R_DIM];
    smid[tid] = g_mid[(size_t)g0 * R_DIM + tid];
    __syncthreads();

    float4 acc[TB2];
#pragma unroll
    for (int t = 0; t < 8; t++)
        acc[t] = __ldcs((const float4*)(result + (size_t)(g0 + t) * H_DIM + h4));

#pragma unroll
    for (int r = 0; r < R_DIM; r++) {
        const float4 b4 = *(const float4*)(btBase + (size_t)r * H_DIM + h4);
#pragma unroll
        for (int t = 0; t < 8; t++) {
            const float m = smid[t * R_DIM + r];
            acc[t].x += m * b4.x;
            acc[t].y += m * b4.y;
            acc[t].z += m * b4.z;
            acc[t].w += m * b4.w;
        }
    }
#pragma unroll
    for (int t = 0; t < 8; t++)
        __stcs((float4*)(out + (size_t)(g0 + t) * H_DIM + h4), acc[t]);

#pragma unroll
    for (int t = 8; t < TB2; t++)
        acc[t] = __ldcs((const float4*)(result + (size_t)(g0 + t) * H_DIM + h4));

#pragma unroll
    for (int r = 0; r < R_DIM; r++) {
        const float4 b4 = *(const float4*)(btBase + (size_t)r * H_DIM + h4);
#pragma unroll
        for (int t = 8; t < TB2; t++) {
            const float m = smid[t * R_DIM + r];
            acc[t].x += m * b4.x;
            acc[t].y += m * b4.y;
            acc[t].z += m * b4.z;
            acc[t].w += m * b4.w;
        }
    }
#pragma unroll
    for (int t = 8; t < TB2; t++)
        __stcs((float4*)(out + (size_t)(g0 + t) * H_DIM + h4), acc[t]);
}

// ---------------------------------------------------------------------------
extern "C" void kernel_launch(void* const* d_in, const int* in_sizes, int n_in,
                              void* d_out, int out_size)
{
    const float* result   = (const float*)d_in[0];
    const float* data     = (const float*)d_in[1];
    const float* dropmask = (const float*)d_in[2];
    const float* lora_a   = (const float*)d_in[3];
    const float* lora_b   = (const float*)d_in[4];
    float* out = (float*)d_out;

    transpose_b_kernel<<<(8 * R_DIM * H_DIM) / NTHREADS, NTHREADS>>>(lora_b);
    lora_mid_kernel<<<N_TOK / K1_TB, NTHREADS>>>(data, dropmask, lora_a);

    dim3 grid2(N_TOK / TB2, H_DIM / (4 * NTHREADS));
    lora_out_kernel<<<grid2, NTHREADS>>>(result, out);
}